// round 16
// baseline (speedup 1.0000x reference)
#include <cuda_runtime.h>
#include <cuda_bf16.h>
#include <math.h>

#define VOCAB 100000
#define EMB   100
#define HID   100
#define CTX   60
#define FACT  20
#define T     60
#define NTILES 782        // ceil(100000 / 128)
#define NWORK  147        // worker blocks in k_main
#define KPAD  112         // K padded for bf16 k16 steps (7 steps)
#define BROW  116         // g_wb row stride in bf16 (232B: conflict-free grp strides)

typedef unsigned long long u64;
typedef unsigned int u32;

// ---------------- scratch ----------------
__device__ float g_facts[CTX * EMB];
__device__ float g_h0[HID];
__device__ float g_gi[T * 3 * HID];
__device__ float g_H[T * HID];
__device__ float g_sumexp[T];
__device__ int   g_flag;
__device__ int   g_cnt0;      // h0 rows done
__device__ int   g_cnt1;      // worker blocks done
__device__ __nv_bfloat16 g_wb[NTILES * 128 * BROW];   // bf16 w_out, padded (23.2MB)

__device__ __forceinline__ float sigmoidf_(float x) {
    return 1.0f / (1.0f + __expf(-x));
}
__device__ __forceinline__ void ffma2(u64 &d, u64 a, u64 b) {
    asm("fma.rn.f32x2 %0, %1, %2, %0;" : "+l"(d) : "l"(a), "l"(b));
}
__device__ __forceinline__ float f2_lo(u64 v) { return __int_as_float((int)(v & 0xffffffffull)); }
__device__ __forceinline__ float f2_hi(u64 v) { return __int_as_float((int)(v >> 32)); }
__device__ __forceinline__ void mma_bf16(float* c, const unsigned* a, const unsigned* b) {
    asm volatile(
        "mma.sync.aligned.m16n8k16.row.col.f32.bf16.bf16.f32 "
        "{%0,%1,%2,%3}, {%4,%5,%6,%7}, {%8,%9}, {%0,%1,%2,%3};"
        : "+f"(c[0]), "+f"(c[1]), "+f"(c[2]), "+f"(c[3])
        : "r"(a[0]), "r"(a[1]), "r"(a[2]), "r"(a[3]), "r"(b[0]), "r"(b[1]));
}
__device__ __forceinline__ u32 s2u(const void* p) {
    return (u32)__cvta_generic_to_shared(p);
}
__device__ __forceinline__ void ldsm_x4(unsigned* r, u32 addr) {
    asm volatile("ldmatrix.sync.aligned.m8n8.x4.shared.b16 {%0,%1,%2,%3}, [%4];"
                 : "=r"(r[0]), "=r"(r[1]), "=r"(r[2]), "=r"(r[3]) : "r"(addr));
}
__device__ __forceinline__ void mbar_init(u32 addr, u32 cnt) {
    asm volatile("mbarrier.init.shared.b64 [%0], %1;" :: "r"(addr), "r"(cnt) : "memory");
}
__device__ __forceinline__ void mbar_expect(u32 addr, u32 bytes) {
    asm volatile("mbarrier.arrive.expect_tx.shared.b64 _, [%0], %1;"
                 :: "r"(addr), "r"(bytes) : "memory");
}
__device__ __forceinline__ void bulk_g2s(u32 dst, const void* src, u32 bytes, u32 mbar) {
    asm volatile("cp.async.bulk.shared::cta.global.mbarrier::complete_tx::bytes [%0], [%1], %2, [%3];"
                 :: "r"(dst), "l"(src), "r"(bytes), "r"(mbar) : "memory");
}
__device__ __forceinline__ void mbar_wait(u32 addr, u32 parity) {
    asm volatile(
        "{\n\t"
        ".reg .pred P;\n\t"
        "WAIT_%=:\n\t"
        "mbarrier.try_wait.parity.acquire.cta.shared::cta.b64 P, [%0], %1, 0x989680;\n\t"
        "@P bra.uni DONE_%=;\n\t"
        "bra.uni WAIT_%=;\n\t"
        "DONE_%=:\n\t"
        "}"
        :: "r"(addr), "r"(parity) : "memory");
}
__device__ __forceinline__ void fence_proxy_async_g() {
    asm volatile("fence.proxy.async;" ::: "memory");
}

// ---------------- K_pre: gi (blocks 0..59) + facts (blocks 60..119) + resets ----------------
__global__ void __launch_bounds__(320) k_pre(const int* __restrict__ ctx,
                                             const float* __restrict__ emb_ctx,
                                             const int* __restrict__ desc,
                                             const float* __restrict__ emb_dec,
                                             const float* __restrict__ w_ih,
                                             const float* __restrict__ b_ih) {
    int bid = blockIdx.x;
    int j = threadIdx.x;
    if (bid < 60) {
        int t = bid;
        __shared__ __align__(16) float x[EMB];
        __shared__ int tok;
        if (j == 0) tok = (t == 0) ? 1 : desc[t - 1];
        __syncthreads();
        if (j < EMB) x[j] = emb_dec[(long)tok * EMB + j];
        __syncthreads();
        if (j < 3 * HID) {
            const float4* w4 = (const float4*)(w_ih + (long)j * EMB);
            const float4* x4 = (const float4*)x;
            float a0 = b_ih[j], a1 = 0.0f, a2 = 0.0f, a3 = 0.0f;
#pragma unroll
            for (int k = 0; k < 25; k++) {
                float4 w = w4[k];
                float4 h = x4[k];
                a0 += w.x * h.x; a1 += w.y * h.y; a2 += w.z * h.z; a3 += w.w * h.w;
            }
            g_gi[t * (3 * HID) + j] = (a0 + a1) + (a2 + a3);
        }
    } else {
        int f = bid - 60;
        if (f == 0 && j < T) g_sumexp[j] = 0.0f;
        if (f == 0 && j == 0) { g_flag = 0; g_cnt0 = 0; g_cnt1 = 0; }
        __shared__ int toks[FACT];
        if (j < FACT) toks[j] = ctx[f * FACT + j];
        __syncthreads();
        if (j < EMB) {
            float ee = (float)j * (1.0f / 99.0f);
            float acc = 0.0f;
#pragma unroll
            for (int p = 0; p < FACT; p++) {
                float s = (float)p * (1.0f / 19.0f);
                float l = 1.0f - s - ee * (1.0f - 2.0f * s);
                acc += emb_ctx[(long)toks[p] * EMB + j] * l;
            }
            g_facts[f * EMB + j] = acc;
        }
    }
}

// ---------------- K_main smem layout (floats) ----------------
// workers: sA bf16 64x112 (3584f) | sB0 bf16 128x116 (7424f) | sB1 (7424f)
//          | bias0 128 | bias1 128 | sSum 512 | mbar 4
#define OFF_SB0 3584
#define OFF_SB1 (OFF_SB0 + 7424)
#define OFF_BI0 (OFF_SB1 + 7424)
#define OFF_BI1 (OFF_BI0 + 128)
#define OFF_SUM (OFF_BI1 + 128)
#define OFF_MBAR (OFF_SUM + 64 * 8)
#define MAIN_SMEM_FLOATS (OFF_MBAR + 4)      // 19204 floats = 76816 B
// block 0 needs 18000+100+600+64+2 = 18766 floats < 19204 ✓

__global__ void __launch_bounds__(600, 1) k_main(const float* __restrict__ w_hh,
                                                 const float* __restrict__ b_hh,
                                                 const float* __restrict__ w_out,
                                                 const float* __restrict__ b_out,
                                                 const float* __restrict__ w1,
                                                 const float* __restrict__ b1,
                                                 const int* __restrict__ desc,
                                                 float* __restrict__ out) {
    extern __shared__ __align__(16) float dyn[];
    int tid = threadIdx.x;

    if (blockIdx.x == 0) {
        // ================= GRU recurrence + token logits + final loss =================
        float* sgi = dyn;            // 18000
        float* h   = dyn + 18000;    // 100
        float* ps  = h + 100;        // 600
        float* tl  = ps + 600;       // 64
        float* red = tl + 64;        // 2

        int outj = tid % 300;
        int half = tid / 300;

        u64 w2[25];
        {
            const u64* wr = (const u64*)(w_hh + (long)outj * HID + half * 50);
#pragma unroll
            for (int k = 0; k < 25; k++) w2[k] = wr[k];
        }
        float bhr = 0.0f, bhz = 0.0f, bhn = 0.0f;
        if (tid < HID) {
            bhr = b_hh[tid];
            bhz = b_hh[HID + tid];
            bhn = b_hh[2 * HID + tid];
        }

        for (int i = tid; i < T * 3 * HID; i += 600) sgi[i] = g_gi[i];

        if (tid == 0) {
            while (*(volatile int*)&g_cnt0 < 100) __nanosleep(32);
        }
        __syncthreads();
        __threadfence();
        if (tid < HID) h[tid] = *((volatile float*)&g_h0[tid]);
        __syncthreads();

        for (int t = 0; t < T; t++) {
            float gir = 0.0f, giz = 0.0f, gin_ = 0.0f;
            if (tid < HID) {
                const float* gi = sgi + t * 300;
                gir  = gi[tid];
                giz  = gi[HID + tid];
                gin_ = gi[2 * HID + tid];
            }
            {
                const u64* h2 = (const u64*)(h + half * 50);
                u64 a0 = 0ull, a1 = 0ull;
#pragma unroll
                for (int k = 0; k < 12; k++) {
                    ffma2(a0, w2[2 * k], h2[2 * k]);
                    ffma2(a1, w2[2 * k + 1], h2[2 * k + 1]);
                }
                ffma2(a0, w2[24], h2[24]);
                ps[tid] = (f2_lo(a0) + f2_hi(a0)) + (f2_lo(a1) + f2_hi(a1));
            }
            __syncthreads();

            if (tid < HID) {
                float ghr = ps[tid]       + ps[tid + 300] + bhr;
                float ghz = ps[tid + 100] + ps[tid + 400] + bhz;
                float ghn = ps[tid + 200] + ps[tid + 500] + bhn;
                float r = sigmoidf_(gir + ghr);
                float z = sigmoidf_(giz + ghz);
                float a = gin_ + r * ghn;
                float ex = __expf(2.0f * a);
                float n = 1.0f - __fdividef(2.0f, ex + 1.0f);
                float hn = (1.0f - z) * n + z * h[tid];
                h[tid] = hn;
                g_H[t * HID + tid] = hn;
            }
            __syncthreads();
        }
        __threadfence();
        __syncthreads();
        if (tid == 0) *(volatile int*)&g_flag = 1;

        // ---- token logits in fp32 (overlaps workers' GEMM) ----
        {
            int wid = tid >> 5;
            int lane = tid & 31;
            if (wid < 15) {
#pragma unroll
                for (int i = 0; i < 4; i++) {
                    int t = wid * 4 + i;
                    int tok = desc[t];
                    const float* wr = w_out + (size_t)tok * HID;
                    const float* hr = g_H + t * HID;
                    float acc = wr[lane] * hr[lane]
                              + wr[lane + 32] * hr[lane + 32]
                              + wr[lane + 64] * hr[lane + 64];
                    if (lane < 4) acc += wr[lane + 96] * hr[lane + 96];
#pragma unroll
                    for (int off = 16; off; off >>= 1)
                        acc += __shfl_down_sync(0xffffffffu, acc, off);
                    if (lane == 0) tl[t] = acc + b_out[tok];
                }
            }
        }

        if (tid == 0) {
            while (*(volatile int*)&g_cnt1 < NWORK) __nanosleep(64);
        }
        __syncthreads();
        __threadfence();
        {
            float v = 0.0f;
            if (tid < T) v = logf(((volatile float*)g_sumexp)[tid]) - tl[tid];
            if (tid < 64) {
#pragma unroll
                for (int off = 16; off; off >>= 1)
                    v += __shfl_down_sync(0xffffffffu, v, off);
                if ((tid & 31) == 0) red[tid >> 5] = v;
            }
            __syncthreads();
            if (tid == 0) out[0] = red[0] + red[1];
        }
        return;
    }

    // ================= workers: h0, w_out->bf16 convert, bf16-mma GEMM =================
    __nv_bfloat16* sA = (__nv_bfloat16*)dyn;                 // 64 x 112
    __nv_bfloat16* sBb[2] = { (__nv_bfloat16*)(dyn + OFF_SB0),
                              (__nv_bfloat16*)(dyn + OFF_SB1) };
    float* sBi[2] = { dyn + OFF_BI0, dyn + OFF_BI1 };
    float* sSum = dyn + OFF_SUM;
    u32 mb[2];
    mb[0] = s2u(dyn + OFF_MBAR);
    mb[1] = mb[0] + 8;

    int bix = blockIdx.x - 1;   // 0..146
    int lane = tid & 31;
    int warp = tid >> 5;
    int nmine = (NTILES - 1 - bix) / NWORK + 1;   // 5 or 6

    // ---- h0 row (blocks 1..100) ----
    if (bix < 100) {
        float acc = 0.0f;
        if (tid < 512) {
            const float* wr = w1 + (long)bix * (CTX * HID);
            for (int k = tid; k < CTX * HID; k += 512)
                acc += g_facts[k] * wr[k];
#pragma unroll
            for (int off = 16; off; off >>= 1)
                acc += __shfl_down_sync(0xffffffffu, acc, off);
            if (lane == 0) sSum[warp] = acc;
        }
        __syncthreads();
        if (tid == 0) {
            float tot = 0.0f;
#pragma unroll
            for (int w = 0; w < 16; w++) tot += sSum[w];
            g_h0[bix] = tot + b1[bix];
            __threadfence();
            atomicAdd(&g_cnt0, 1);
        }
        __syncthreads();
    }

    // ---- convert own tiles: w_out fp32 -> g_wb bf16 (padded rows of 116) ----
    // Overlaps the recurrence. Each block owns tiles bix, bix+147, ...
    for (int li = 0; li < nmine; li++) {
        int tile = bix + li * NWORK;
        int N0 = tile * 128;
        __nv_bfloat16* dst = g_wb + (size_t)tile * (128 * BROW);
        for (int i = tid; i < 128 * BROW; i += 600) {
            int n = i / BROW;
            int k = i - n * BROW;
            int gn = N0 + n;
            float v = (gn < VOCAB && k < HID) ? w_out[(size_t)gn * HID + k] : 0.0f;
            dst[i] = __float2bfloat16(v);
        }
    }
    __threadfence();          // make conversions visible to TMA (L2)
    __syncthreads();

    // ---- mbarrier init + pre-stage tiles 0,1 ----
    if (tid == 0) {
        mbar_init(mb[0], 1);
        mbar_init(mb[1], 1);
        fence_proxy_async_g();
    }
    __syncthreads();

    auto stageB = [&](int li) {   // tid 0 only
        int tile = bix + li * NWORK;
        if (tile >= NTILES) return;
        int buf = li & 1;
        int N0 = tile * 128;
        int rows = VOCAB - N0; if (rows > 128) rows = 128;
        u32 wb = 128u * BROW * 2u;          // full padded tile always valid in g_wb
        u32 bb = (u32)rows * 4u;
        mbar_expect(mb[buf], wb + bb);
        bulk_g2s(s2u(sBb[buf]), g_wb + (size_t)tile * (128 * BROW), wb, mb[buf]);
        bulk_g2s(s2u(sBi[buf]), b_out + N0, bb, mb[buf]);
    };

    if (tid == 0) { stageB(0); stageB(1); }

    // ---- wait for full H, stage A (bf16, zero-padded 64x112) ----
    if (tid == 0) {
        while (*(volatile int*)&g_flag < 1) __nanosleep(64);
    }
    __syncthreads();
    __threadfence();
    for (int i = tid; i < 64 * KPAD; i += 600) {
        int m = i / KPAD, k = i - m * KPAD;
        float v = (m < T && k < HID) ? g_H[m * HID + k] : 0.0f;
        sA[i] = __float2bfloat16(v);
    }
    __syncthreads();

    int mg = warp >> 3;        // 0..1 (m32 group)
    int ng = warp & 7;         // 0..7 (n16 group)
    int grp = lane >> 2;       // 0..7
    int qi = lane & 3;         // 0..3

    // ldmatrix lane addresses: A m16xk16 as four 8x8 b16 matrices
    // lane L: j=L>>3 (matrix), r=L&7; row = mbase + (j&1)*8 + r; kcol = (j>>1)*8
    u32 a_addr[2];
#pragma unroll
    for (int mi = 0; mi < 2; mi++) {
        int row = mg * 32 + mi * 16 + ((lane >> 3) & 1) * 8 + (lane & 7);
        a_addr[mi] = s2u(sA + row * KPAD) + (u32)((lane >> 4) * 16);
    }

    float rowsum[4] = {0.f, 0.f, 0.f, 0.f};

#pragma unroll 1
    for (int li = 0; li < nmine; li++) {
        if (tid == 0 && li >= 1) stageB(li + 1);
        mbar_wait(mb[li & 1], (u32)((li >> 1) & 1));

        int tile = bix + li * NWORK;
        int N0 = tile * 128;
        if (N0 + 128 > VOCAB) {
            if (tid < 128 && N0 + tid >= VOCAB) sBi[li & 1][tid] = -1e30f;
            __syncthreads();
        }

        if (tid < 512) {
            const __nv_bfloat16* sB = sBb[li & 1];
            const float* sBias = sBi[li & 1];

            float c[2][2][4];
#pragma unroll
            for (int mi = 0; mi < 2; mi++)
#pragma unroll
                for (int nf = 0; nf < 2; nf++)
#pragma unroll
                    for (int r = 0; r < 4; r++) c[mi][nf][r] = 0.0f;

            // B: row n stride BROW bf16 (232B); b0 at k=2qi (byte 4qi), b1 = +16B
            const char* bbase0 = (const char*)(sB + (ng * 16 + grp) * BROW) + qi * 4;
            const char* bbase1 = bbase0 + 8 * BROW * 2;    // +8 n-rows
#pragma unroll
            for (int kt = 0; kt < 7; kt++) {
                unsigned a[2][4];
                ldsm_x4(a[0], a_addr[0] + kt * 32);
                ldsm_x4(a[1], a_addr[1] + kt * 32);
                unsigned b[2][2];
                b[0][0] = *(const unsigned*)(bbase0 + kt * 32);
                b[0][1] = *(const unsigned*)(bbase0 + kt * 32 + 16);
                b[1][0] = *(const unsigned*)(bbase1 + kt * 32);
                b[1][1] = *(const unsigned*)(bbase1 + kt * 32 + 16);
#pragma unroll
                for (int mi = 0; mi < 2; mi++) {
                    mma_bf16(c[mi][0], a[mi], b[0]);
                    mma_bf16(c[mi][1], a[mi], b[1]);
                }
            }

#pragma unroll
            for (int nf = 0; nf < 2; nf++) {
                int n0 = ng * 16 + nf * 8 + 2 * qi;
                float bias0 = sBias[n0];
                float bias1 = sBias[n0 + 1];
#pragma unroll
                for (int mi = 0; mi < 2; mi++) {
                    rowsum[mi * 2]     += __expf(c[mi][nf][0] + bias0) + __expf(c[mi][nf][1] + bias1);
                    rowsum[mi * 2 + 1] += __expf(c[mi][nf][2] + bias0) + __expf(c[mi][nf][3] + bias1);
                }
            }
        }
        __syncthreads();        // readers done before buffer restage
    }

    // cross-lane reduce over qi and publish
#pragma unroll
    for (int j = 0; j < 4; j++) {
        rowsum[j] += __shfl_xor_sync(0xffffffffu, rowsum[j], 1);
        rowsum[j] += __shfl_xor_sync(0xffffffffu, rowsum[j], 2);
    }
    if (tid < 512 && qi == 0) {
#pragma unroll
        for (int j = 0; j < 4; j++) {
            int row = mg * 32 + (j >> 1) * 16 + (j & 1) * 8 + grp;
            sSum[row * 8 + ng] = rowsum[j];
        }
    }
    __syncthreads();
    if (tid < 64) {
        float s = 0.0f;
#pragma unroll
        for (int w = 0; w < 8; w++) s += sSum[tid * 8 + w];
        if (tid < T) atomicAdd(&g_sumexp[tid], s);
    }
    __threadfence();
    __syncthreads();
    if (tid == 0) atomicAdd(&g_cnt1, 1);
}

// ---------------- launch ----------------
extern "C" void kernel_launch(void* const* d_in, const int* in_sizes, int n_in,
                              void* d_out, int out_size) {
    const int*   context  = (const int*)d_in[0];
    const int*   desc     = (const int*)d_in[2];
    const float* emb_ctx  = (const float*)d_in[3];
    const float* emb_dec  = (const float*)d_in[4];
    const float* w1       = (const float*)d_in[5];
    const float* b1       = (const float*)d_in[6];
    const float* w_ih     = (const float*)d_in[7];
    const float* w_hh     = (const float*)d_in[8];
    const float* b_ih     = (const float*)d_in[9];
    const float* b_hh     = (const float*)d_in[10];
    const float* w_out    = (const float*)d_in[11];
    const float* b_out    = (const float*)d_in[12];
    float* out = (float*)d_out;

    const int main_smem = MAIN_SMEM_FLOATS * (int)sizeof(float);   // 76816 B
    cudaFuncSetAttribute(k_main, cudaFuncAttributeMaxDynamicSharedMemorySize, main_smem);

    k_pre<<<120, 320>>>(context, emb_ctx, desc, emb_dec, w_ih, b_ih);
    k_main<<<148, 600, main_smem>>>(w_hh, b_hh, w_out, b_out, w1, b1, desc, out);
}

// round 17
// speedup vs baseline: 1.1000x; 1.1000x over previous
#include <cuda_runtime.h>
#include <math.h>

#define VOCAB 100000
#define EMB   100
#define HID   100
#define CTX   60
#define FACT  20
#define T     60
#define NTILES 782        // ceil(100000 / 128)
#define NWORK  147        // logits worker blocks

typedef unsigned long long u64;
typedef unsigned int u32;

// ---------------- scratch ----------------
__device__ float g_facts[CTX * EMB];
__device__ float g_h0[HID];
__device__ float g_gi[T * 3 * HID];
__device__ float g_H[T * HID];
__device__ float g_sumexp[T];
__device__ int   g_flag;
__device__ int   g_cnt0;      // h0 rows done
__device__ int   g_cnt1;      // worker blocks done

__device__ __forceinline__ float sigmoidf_(float x) {
    return 1.0f / (1.0f + __expf(-x));
}
__device__ __forceinline__ void ffma2(u64 &d, u64 a, u64 b) {
    asm("fma.rn.f32x2 %0, %1, %2, %0;" : "+l"(d) : "l"(a), "l"(b));
}
__device__ __forceinline__ float f2_lo(u64 v) { return __int_as_float((int)(v & 0xffffffffull)); }
__device__ __forceinline__ float f2_hi(u64 v) { return __int_as_float((int)(v >> 32)); }
__device__ __forceinline__ u64 f2_pack(float x, float y) {
    return (u64)__float_as_uint(x) | ((u64)__float_as_uint(y) << 32);
}
__device__ __forceinline__ unsigned to_tf32(float f) {
    unsigned r;
    asm("cvt.rna.tf32.f32 %0, %1;" : "=r"(r) : "f"(f));
    return r;
}
__device__ __forceinline__ void mma_tf32(float* c, const unsigned* a, const unsigned* b) {
    asm volatile(
        "mma.sync.aligned.m16n8k8.row.col.f32.tf32.tf32.f32 "
        "{%0,%1,%2,%3}, {%4,%5,%6,%7}, {%8,%9}, {%0,%1,%2,%3};"
        : "+f"(c[0]), "+f"(c[1]), "+f"(c[2]), "+f"(c[3])
        : "r"(a[0]), "r"(a[1]), "r"(a[2]), "r"(a[3]), "r"(b[0]), "r"(b[1]));
}
__device__ __forceinline__ u32 s2u(const void* p) {
    return (u32)__cvta_generic_to_shared(p);
}
__device__ __forceinline__ void ldsm_x4(unsigned* r, u32 addr) {
    asm volatile("ldmatrix.sync.aligned.m8n8.x4.shared.b16 {%0,%1,%2,%3}, [%4];"
                 : "=r"(r[0]), "=r"(r[1]), "=r"(r[2]), "=r"(r[3]) : "r"(addr));
}
__device__ __forceinline__ void ldsm_x2(unsigned* r, u32 addr) {
    asm volatile("ldmatrix.sync.aligned.m8n8.x2.shared.b16 {%0,%1}, [%2];"
                 : "=r"(r[0]), "=r"(r[1]) : "r"(addr));
}
__device__ __forceinline__ void mbar_init(u32 addr, u32 cnt) {
    asm volatile("mbarrier.init.shared.b64 [%0], %1;" :: "r"(addr), "r"(cnt) : "memory");
}
__device__ __forceinline__ void mbar_expect(u32 addr, u32 bytes) {
    asm volatile("mbarrier.arrive.expect_tx.shared.b64 _, [%0], %1;"
                 :: "r"(addr), "r"(bytes) : "memory");
}
__device__ __forceinline__ void bulk_g2s(u32 dst, const void* src, u32 bytes, u32 mbar) {
    asm volatile("cp.async.bulk.shared::cta.global.mbarrier::complete_tx::bytes [%0], [%1], %2, [%3];"
                 :: "r"(dst), "l"(src), "r"(bytes), "r"(mbar) : "memory");
}
__device__ __forceinline__ void mbar_wait(u32 addr, u32 parity) {
    asm volatile(
        "{\n\t"
        ".reg .pred P;\n\t"
        "WAIT_%=:\n\t"
        "mbarrier.try_wait.parity.acquire.cta.shared::cta.b64 P, [%0], %1, 0x989680;\n\t"
        "@P bra.uni DONE_%=;\n\t"
        "bra.uni WAIT_%=;\n\t"
        "DONE_%=:\n\t"
        "}"
        :: "r"(addr), "r"(parity) : "memory");
}
__device__ __forceinline__ void fence_proxy_async_cta() {
    asm volatile("fence.proxy.async.shared::cta;" ::: "memory");
}

// ---------------- K_pre: gi (blocks 0..59) + facts (blocks 60..119) + resets ----------------
__global__ void __launch_bounds__(320) k_pre(const int* __restrict__ ctx,
                                             const float* __restrict__ emb_ctx,
                                             const int* __restrict__ desc,
                                             const float* __restrict__ emb_dec,
                                             const float* __restrict__ w_ih,
                                             const float* __restrict__ b_ih) {
    int bid = blockIdx.x;
    int j = threadIdx.x;
    if (bid < 60) {
        int t = bid;
        __shared__ __align__(16) float x[EMB];
        __shared__ int tok;
        if (j == 0) tok = (t == 0) ? 1 : desc[t - 1];
        __syncthreads();
        if (j < EMB) x[j] = emb_dec[(long)tok * EMB + j];
        __syncthreads();
        if (j < 3 * HID) {
            const float4* w4 = (const float4*)(w_ih + (long)j * EMB);
            const float4* x4 = (const float4*)x;
            float a0 = b_ih[j], a1 = 0.0f, a2 = 0.0f, a3 = 0.0f;
#pragma unroll
            for (int k = 0; k < 25; k++) {
                float4 w = w4[k];
                float4 h = x4[k];
                a0 += w.x * h.x; a1 += w.y * h.y; a2 += w.z * h.z; a3 += w.w * h.w;
            }
            g_gi[t * (3 * HID) + j] = (a0 + a1) + (a2 + a3);
        }
    } else {
        int f = bid - 60;
        if (f == 0 && j < T) g_sumexp[j] = 0.0f;
        if (f == 0 && j == 0) { g_flag = 0; g_cnt0 = 0; g_cnt1 = 0; }
        __shared__ int toks[FACT];
        if (j < FACT) toks[j] = ctx[f * FACT + j];
        __syncthreads();
        if (j < EMB) {
            float ee = (float)j * (1.0f / 99.0f);
            float acc = 0.0f;
#pragma unroll
            for (int p = 0; p < FACT; p++) {
                float s = (float)p * (1.0f / 19.0f);
                float l = 1.0f - s - ee * (1.0f - 2.0f * s);
                acc += emb_ctx[(long)toks[p] * EMB + j] * l;
            }
            g_facts[f * EMB + j] = acc;
        }
    }
}

// ---------------- K_main smem layout (floats) ----------------
#define SA_F    (64 * 108)                  // 6912
#define SBN_F   (128 * 100 + 4)             // 12804
#define OFF_SB0 (SA_F)
#define OFF_SB1 (OFF_SB0 + SBN_F)
#define OFF_BI0 (OFF_SB1 + SBN_F)
#define OFF_BI1 (OFF_BI0 + 128)
#define OFF_SUM (OFF_BI1 + 128)
#define OFF_MBAR (OFF_SUM + 64 * 8)
#define MAIN_SMEM_FLOATS (OFF_MBAR + 4)

__global__ void __launch_bounds__(600, 1) k_main(const float* __restrict__ w_hh,
                                                 const float* __restrict__ b_hh,
                                                 const float* __restrict__ w_out,
                                                 const float* __restrict__ b_out,
                                                 const float* __restrict__ w1,
                                                 const float* __restrict__ b1,
                                                 const int* __restrict__ desc,
                                                 float* __restrict__ out) {
    extern __shared__ __align__(16) float dyn[];
    int tid = threadIdx.x;

    if (blockIdx.x == 0) {
        // ================= GRU recurrence + token logits + final loss =================
        float* sgi = dyn;            // 18000
        float* h   = dyn + 18000;    // 100
        float* ps  = h + 100;        // 600
        float* tl  = ps + 600;       // 64
        float* red = tl + 64;        // 2

        int outj = tid % 300;
        int half = tid / 300;
        int kbeg = half ? 52 : 0;    // 16B-aligned split (R12 form — measured best)

        u64 w2[26];
        {
            const double2* wr = (const double2*)(w_hh + (long)outj * HID + kbeg);
#pragma unroll
            for (int k = 0; k < 13; k++) {
                if (k + half < 13) {
                    double2 d = wr[k];
                    w2[2 * k]     = (u64)__double_as_longlong(d.x);
                    w2[2 * k + 1] = (u64)__double_as_longlong(d.y);
                }
            }
        }
        float bhr = 0.0f, bhz = 0.0f, bhn = 0.0f;
        if (tid < HID) {
            bhr = b_hh[tid];
            bhz = b_hh[HID + tid];
            bhn = b_hh[2 * HID + tid];
        }

        for (int i = tid; i < T * 3 * HID; i += 600) sgi[i] = g_gi[i];

        if (tid == 0) {
            while (*(volatile int*)&g_cnt0 < 100) __nanosleep(32);
        }
        __syncthreads();
        __threadfence();
        if (tid < HID) h[tid] = *((volatile float*)&g_h0[tid]);
        __syncthreads();

        const double2* h2 = (const double2*)(h + kbeg);
        for (int t = 0; t < T; t++) {
            {
                u64 a0 = 0ull, a1 = 0ull;
#pragma unroll
                for (int k = 0; k < 13; k++) {
                    if (k + half < 13) {
                        double2 d = h2[k];
                        ffma2(a0, w2[2 * k],     (u64)__double_as_longlong(d.x));
                        ffma2(a1, w2[2 * k + 1], (u64)__double_as_longlong(d.y));
                    }
                }
                ps[tid] = (f2_lo(a0) + f2_hi(a0)) + (f2_lo(a1) + f2_hi(a1));
            }
            __syncthreads();

            if (tid < HID) {
                float ghr = ps[tid]       + ps[tid + 300] + bhr;
                float ghz = ps[tid + 100] + ps[tid + 400] + bhz;
                float ghn = ps[tid + 200] + ps[tid + 500] + bhn;
                const float* gi = sgi + t * 300;
                float r = sigmoidf_(gi[tid] + ghr);
                float z = sigmoidf_(gi[HID + tid] + ghz);
                float a = gi[2 * HID + tid] + r * ghn;
                float ex = __expf(2.0f * a);
                float n = 1.0f - __fdividef(2.0f, ex + 1.0f);
                float hn = (1.0f - z) * n + z * h[tid];
                h[tid] = hn;
                g_H[t * HID + tid] = hn;
            }
            if (t == 31) {
                __threadfence();
                __syncthreads();
                if (tid == 0) *(volatile int*)&g_flag = 1;
            } else {
                __syncthreads();
            }
        }
        __threadfence();
        __syncthreads();
        if (tid == 0) *(volatile int*)&g_flag = 2;

        // ---- token logits (overlaps workers' pass B) ----
        {
            int wid = tid >> 5;
            int lane = tid & 31;
            if (wid < 15) {
#pragma unroll
                for (int i = 0; i < 4; i++) {
                    int t = wid * 4 + i;
                    int tok = desc[t];
                    const float* wr = w_out + (size_t)tok * HID;
                    const float* hr = g_H + t * HID;
                    float acc = wr[lane] * hr[lane]
                              + wr[lane + 32] * hr[lane + 32]
                              + wr[lane + 64] * hr[lane + 64];
                    if (lane < 4) acc += wr[lane + 96] * hr[lane + 96];
#pragma unroll
                    for (int off = 16; off; off >>= 1)
                        acc += __shfl_down_sync(0xffffffffu, acc, off);
                    if (lane == 0) tl[t] = acc + b_out[tok];
                }
            }
        }

        if (tid == 0) {
            while (*(volatile int*)&g_cnt1 < NWORK) __nanosleep(64);
        }
        __syncthreads();
        __threadfence();
        {
            float v = 0.0f;
            if (tid < T) v = logf(((volatile float*)g_sumexp)[tid]) - tl[tid];
            if (tid < 64) {
#pragma unroll
                for (int off = 16; off; off >>= 1)
                    v += __shfl_down_sync(0xffffffffu, v, off);
                if ((tid & 31) == 0) red[tid >> 5] = v;
            }
            __syncthreads();
            if (tid == 0) out[0] = red[0] + red[1];
        }
        return;
    }

    // ================= workers: h0, 2-pass M=32 GEMM with slot-pipelined bulk TMA =================
    float* sA = dyn;
    float* sBb[2] = { dyn + OFF_SB0, dyn + OFF_SB1 };
    float* sBi[2] = { dyn + OFF_BI0, dyn + OFF_BI1 };
    float* sSum = dyn + OFF_SUM;
    u32 mb[2];
    mb[0] = s2u(dyn + OFF_MBAR);
    mb[1] = mb[0] + 8;

    int bix = blockIdx.x - 1;   // 0..146
    int lane = tid & 31;
    int warp = tid >> 5;
    int nmine = (NTILES - 1 - bix) / NWORK + 1;   // 5 or 6
    int nslots = 2 * nmine;

    // zero both B buffers (pad word hygiene)
    for (int i = tid; i < 2 * SBN_F; i += 600) sBb[0][i] = 0.0f;

    // ---- h0 row (blocks 1..100) ----
    if (bix < 100) {
        float acc = 0.0f;
        if (tid < 512) {
            const float* wr = w1 + (long)bix * (CTX * HID);
            for (int k = tid; k < CTX * HID; k += 512)
                acc += g_facts[k] * wr[k];
#pragma unroll
            for (int off = 16; off; off >>= 1)
                acc += __shfl_down_sync(0xffffffffu, acc, off);
            if (lane == 0) sSum[warp] = acc;
        }
        __syncthreads();
        if (tid == 0) {
            float tot = 0.0f;
#pragma unroll
            for (int w = 0; w < 16; w++) tot += sSum[w];
            g_h0[bix] = tot + b1[bix];
            __threadfence();
            atomicAdd(&g_cnt0, 1);
        }
        __syncthreads();
    } else {
        __syncthreads();
        __syncthreads();
    }

    if (tid == 0) {
        mbar_init(mb[0], 1);
        mbar_init(mb[1], 1);
        fence_proxy_async_cta();
    }
    __syncthreads();

    auto stageB = [&](int slot) {   // tid 0 only; tile repeats across the two passes
        if (slot >= nslots) return;
        int li = slot % nmine;
        int tile = bix + li * NWORK;
        int buf = slot & 1;
        int N0 = tile * 128;
        int rows = VOCAB - N0; if (rows > 128) rows = 128;
        u32 wb = (u32)rows * 400u;
        u32 bb = (u32)rows * 4u;
        mbar_expect(mb[buf], wb + bb);
        bulk_g2s(s2u(sBb[buf]), w_out + (size_t)N0 * HID, wb, mb[buf]);
        bulk_g2s(s2u(sBi[buf]), b_out + N0, bb, mb[buf]);
    };

    if (tid == 0) { stageB(0); stageB(1); }

    int mg = warp >> 3;        // 0..1 (m16 group within the pass's 32 rows)
    int ng = warp & 7;         // 0..7 (n16 group)
    int grp = lane >> 2;       // 0..7
    int qi = lane & 3;         // 0..3

    float rowsum[4] = {0.f, 0.f, 0.f, 0.f};   // [pass*2 + (0: row grp, 1: row grp+8)]

#pragma unroll 1
    for (int pass = 0; pass < 2; pass++) {
        // wait for H rows [pass*32, pass*32+32)
        if (tid == 0) {
            while (*(volatile int*)&g_flag < pass + 1) __nanosleep(64);
        }
        __syncthreads();
        __threadfence();

        // stage A rows for this pass (tf32, zero-padded into 64x108 buffer)
        for (int i = tid; i < 32 * 108; i += 600) {
            int m = i / 108, k = i - m * 108;
            int row = pass * 32 + m;
            float v = (row < T && k < HID) ? g_H[row * HID + k] : 0.0f;
            sA[row * 108 + k] = __uint_as_float(to_tf32(v));
        }
        __syncthreads();

        u32 a_addr = s2u(sA + (pass * 32 + mg * 16 + (lane & 15)) * 108 + 4 * (lane >> 4));

#pragma unroll 1
        for (int li = 0; li < nmine; li++) {
            int slot = pass * nmine + li;
            if (tid == 0 && slot >= 1) stageB(slot + 1);
            mbar_wait(mb[slot & 1], (u32)((slot >> 1) & 1));

            int tile = bix + li * NWORK;
            int N0 = tile * 128;
            if (N0 + 128 > VOCAB) {
                if (tid < 128 && N0 + tid >= VOCAB) sBi[slot & 1][tid] = -1e30f;
                __syncthreads();
            }

            if (tid < 512) {
                const float* sB = sBb[slot & 1];
                const float* sBias = sBi[slot & 1];

                float c[2][4];
#pragma unroll
                for (int nf = 0; nf < 2; nf++)
#pragma unroll
                    for (int r = 0; r < 4; r++) c[nf][r] = 0.0f;

                const float* bbase = sB + (ng * 16 + grp) * 100 + qi;
#pragma unroll
                for (int kt = 0; kt < 13; kt++) {
                    unsigned a[4];
                    ldsm_x4(a, a_addr + kt * 32);
                    unsigned b[2][2];
                    const float* bp = bbase + kt * 8;
                    b[0][0] = __float_as_uint(bp[0]);
                    b[0][1] = __float_as_uint(bp[4]);
                    b[1][0] = __float_as_uint(bp[800]);
                    b[1][1] = __float_as_uint(bp[804]);
                    mma_tf32(c[0], a, b[0]);
                    mma_tf32(c[1], a, b[1]);
                }

#pragma unroll
                for (int nf = 0; nf < 2; nf++) {
                    int n0 = ng * 16 + nf * 8 + 2 * qi;
                    float bias0 = sBias[n0];
                    float bias1 = sBias[n0 + 1];
                    rowsum[pass * 2]     += __expf(c[nf][0] + bias0) + __expf(c[nf][1] + bias1);
                    rowsum[pass * 2 + 1] += __expf(c[nf][2] + bias0) + __expf(c[nf][3] + bias1);
                }
            }
            __syncthreads();        // readers done before buffer restage
        }
    }

    // cross-lane reduce over qi and publish
#pragma unroll
    for (int j = 0; j < 4; j++) {
        rowsum[j] += __shfl_xor_sync(0xffffffffu, rowsum[j], 1);
        rowsum[j] += __shfl_xor_sync(0xffffffffu, rowsum[j], 2);
    }
    if (tid < 512 && qi == 0) {
#pragma unroll
        for (int j = 0; j < 4; j++) {
            int row = (j >> 1) * 32 + mg * 16 + (j & 1) * 8 + grp;
            sSum[row * 8 + ng] = rowsum[j];
        }
    }
    __syncthreads();
    if (tid < 64) {
        float s = 0.0f;
#pragma unroll
        for (int w = 0; w < 8; w++) s += sSum[tid * 8 + w];
        if (tid < T) atomicAdd(&g_sumexp[tid], s);
    }
    __threadfence();
    __syncthreads();
    if (tid == 0) atomicAdd(&g_cnt1, 1);
}

// ---------------- launch ----------------
extern "C" void kernel_launch(void* const* d_in, const int* in_sizes, int n_in,
                              void* d_out, int out_size) {
    const int*   context  = (const int*)d_in[0];
    const int*   desc     = (const int*)d_in[2];
    const float* emb_ctx  = (const float*)d_in[3];
    const float* emb_dec  = (const float*)d_in[4];
    const float* w1       = (const float*)d_in[5];
    const float* b1       = (const float*)d_in[6];
    const float* w_ih     = (const float*)d_in[7];
    const float* w_hh     = (const float*)d_in[8];
    const float* b_ih     = (const float*)d_in[9];
    const float* b_hh     = (const float*)d_in[10];
    const float* w_out    = (const float*)d_in[11];
    const float* b_out    = (const float*)d_in[12];
    float* out = (float*)d_out;

    const int main_smem = MAIN_SMEM_FLOATS * (int)sizeof(float);   // 133168 B
    cudaFuncSetAttribute(k_main, cudaFuncAttributeMaxDynamicSharedMemorySize, main_smem);

    k_pre<<<120, 320>>>(context, emb_ctx, desc, emb_dec, w_ih, b_ih);
    k_main<<<148, 600, main_smem>>>(w_hh, b_hh, w_out, b_out, w1, b1, desc, out);
}